// round 15
// baseline (speedup 1.0000x reference)
#include <cuda_runtime.h>
#include <cstdint>

#define IN_F  4096
#define OUT_F 16384
#define NB    8      // batch vectors
#define NP    (NB/2) // batch pairs
#define RPW   8      // rows per warp
#define WARPS 4
#define THREADS (WARPS * 32)          // 128
#define ROWS_PER_CTA (RPW * WARPS)    // 32
#define NCHUNK (IN_F / 128)           // 32 chunks (4 cols/lane each)
#define AROW   (IN_F / 64)            // absmax row stride (64)
#define XSTG   512                    // ull per x stage (4 pairs x 128 cols)

__constant__ float NF4_CODE[16] = {
    -1.0f, -0.6961928009986877f, -0.5250730514526367f, -0.39491748809814453f,
    -0.28444138169288635f, -0.18477343022823334f, -0.09105003625154495f, 0.0f,
    0.07958029955625534f, 0.16093020141124725f, 0.24611230194568634f,
    0.33791524171829224f, 0.44070982933044434f, 0.5626170039176941f,
    0.7229568362236023f, 1.0f};

typedef unsigned long long ull;

// cross-batch packed x: g_xT[p*IN_F + col] = (x[2p][col], x[2p+1][col])
__device__ ull g_xT[NP * IN_F];

__device__ __forceinline__ ull pk2(float lo, float hi) {
    ull r;
    asm("mov.b64 %0, {%1, %2};" : "=l"(r)
        : "r"(__float_as_uint(lo)), "r"(__float_as_uint(hi)));
    return r;
}
__device__ __forceinline__ void upk2(ull v, float& lo, float& hi) {
    unsigned int a, b;
    asm("mov.b64 {%0, %1}, %2;" : "=r"(a), "=r"(b) : "l"(v));
    lo = __uint_as_float(a); hi = __uint_as_float(b);
}
__device__ __forceinline__ void fma2(ull& acc, ull a, ull b) {
    asm("fma.rn.f32x2 %0, %1, %2, %0;" : "+l"(acc) : "l"(a), "l"(b));
}
__device__ __forceinline__ ull mul2(ull a, ull b) {
    ull r;
    asm("mul.rn.f32x2 %0, %1, %2;" : "=l"(r) : "l"(a), "l"(b));
    return r;
}

// ---- prepass: build cross-batch packed x (once per launch, ~1.5us) ----
__global__ void xt_kernel(const float* __restrict__ x) {
    const int idx = blockIdx.x * 256 + threadIdx.x;   // 0 .. NP*IN_F-1
    const int p   = idx >> 12;
    const int col = idx & (IN_F - 1);
    g_xT[idx] = pk2(x[(2 * p) * IN_F + col], x[(2 * p + 1) * IN_F + col]);
}

__global__ __launch_bounds__(THREADS, 2)
void nf4_qlinear_kernel(const int*   __restrict__ codes,
                        const float* __restrict__ absmax,
                        float*       __restrict__ out) {
    // splat NF4 table (conflict-free LDS.64) + 3 x-stages (4 KB each)
    __shared__ ull tabS[16];
    __shared__ ull xstg[3][XSTG];
    const int tid  = threadIdx.x;
    const int lane = tid & 31;
    const int warp = tid >> 5;
    if (tid < 16) tabS[tid] = pk2(NF4_CODE[tid], NF4_CODE[tid]);

    const int row0   = blockIdx.x * ROWS_PER_CTA + warp * RPW;
    const int sel_hi = (lane >= 16);

    // pointer-bump bases (all loads reg + const-immediate offsets)
    const int4*  cp = reinterpret_cast<const int4*>(
                          codes + (size_t)row0 * IN_F) + lane;
    const float* ap = absmax + (size_t)row0 * AROW + sel_hi;

    // ---- x stage fill: thread t copies 32 B of pair (t>>5), cols (t&31)*4 ----
    const int fp  = tid >> 5;          // pair handled by this thread
    const int fcb = (tid & 31) * 4;    // column base
    const ull* fsrc0 = g_xT + (size_t)fp * IN_F + fcb;
    auto fill = [&](int jj) {
        const unsigned d = (unsigned)__cvta_generic_to_shared(
            &xstg[jj % 3][fp * 128 + fcb]);
        const ull* s = fsrc0 + jj * 128;
        asm volatile("cp.async.ca.shared.global [%0], [%1], 16;\n"
                     :: "r"(d), "l"(s));
        asm volatile("cp.async.ca.shared.global [%0], [%1], 16;\n"
                     :: "r"(d + 16), "l"(s + 2));
        asm volatile("cp.async.commit_group;\n" ::: "memory");
    };

    ull acc[RPW][NP];    // acc[r][p] packs (batch 2p, batch 2p+1)
    #pragma unroll
    for (int r = 0; r < RPW; ++r)
        #pragma unroll
        for (int p = 0; p < NP; ++p) acc[r][p] = 0ULL;

    // ---- consume one chunk: codes/absmax from regs, x from smem stage ----
    auto consume = [&](const int4* cv, const float* am, const ull* sx) {
        ull xq0[NP], xq1[NP], xq2[NP], xq3[NP];
        #pragma unroll
        for (int p = 0; p < NP; ++p) {
            const ulonglong2 xv0 = *reinterpret_cast<const ulonglong2*>(
                sx + p * 128 + lane * 4);
            const ulonglong2 xv1 = *reinterpret_cast<const ulonglong2*>(
                sx + p * 128 + lane * 4 + 2);
            xq0[p] = xv0.x; xq1[p] = xv0.y;
            xq2[p] = xv1.x; xq3[p] = xv1.y;
        }
        #pragma unroll
        for (int r = 0; r < RPW; ++r) {
            const ull a2 = pk2(am[r], am[r]);
            const ull s0 = mul2(tabS[cv[r].x], a2);
            const ull s1 = mul2(tabS[cv[r].y], a2);
            const ull s2 = mul2(tabS[cv[r].z], a2);
            const ull s3 = mul2(tabS[cv[r].w], a2);
            #pragma unroll
            for (int p = 0; p < NP; ++p) {
                fma2(acc[r][p], s0, xq0[p]);
                fma2(acc[r][p], s1, xq1[p]);
                fma2(acc[r][p], s2, xq2[p]);
                fma2(acc[r][p], s3, xq3[p]);
            }
        }
    };

    // ---- prologue: x stages 0,1 + register code/absmax buffers ----
    fill(0);
    fill(1);
    int4  cvA[RPW], cvB[RPW], cvC[RPW];
    float amA[RPW], amB[RPW], amC[RPW];
    #pragma unroll
    for (int r = 0; r < RPW; ++r) {
        cvA[r] = __ldcs(cp + r * (IN_F / 4));
        amA[r] = __ldg(ap + r * AROW);
        cvB[r] = __ldcs(cp + 32 + r * (IN_F / 4));
        amB[r] = __ldg(ap + 2 + r * AROW);
    }
    __syncthreads();   // tabS visible

    #pragma unroll 1
    for (int it = 0; it < 10; ++it) {        // chunks 3*it .. 3*it+2
        const int j = it * 3;
        // ---- chunk j ----
        asm volatile("cp.async.wait_group 1;\n" ::: "memory");
        __syncthreads();
        fill(j + 2);
        #pragma unroll
        for (int r = 0; r < RPW; ++r) {      // prefetch codes j+2
            cvC[r] = __ldcs(cp + 64 + r * (IN_F / 4));
            amC[r] = __ldg(ap + 4 + r * AROW);
        }
        consume(cvA, amA, xstg[j % 3]);
        // ---- chunk j+1 ----
        asm volatile("cp.async.wait_group 1;\n" ::: "memory");
        __syncthreads();
        if (j + 3 < NCHUNK) fill(j + 3);
        else asm volatile("cp.async.commit_group;\n" ::: "memory");
        #pragma unroll
        for (int r = 0; r < RPW; ++r) {      // prefetch codes j+3
            cvA[r] = __ldcs(cp + 96 + r * (IN_F / 4));
            amA[r] = __ldg(ap + 6 + r * AROW);
        }
        consume(cvB, amB, xstg[(j + 1) % 3]);
        // ---- chunk j+2 ----
        asm volatile("cp.async.wait_group 1;\n" ::: "memory");
        __syncthreads();
        if (j + 4 < NCHUNK) fill(j + 4);
        else asm volatile("cp.async.commit_group;\n" ::: "memory");
        #pragma unroll
        for (int r = 0; r < RPW; ++r) {      // prefetch codes j+4
            cvB[r] = __ldcs(cp + 128 + r * (IN_F / 4));
            amB[r] = __ldg(ap + 8 + r * AROW);
        }
        consume(cvC, amC, xstg[(j + 2) % 3]);
        cp += 96;     // 3 chunks
        ap += 6;
    }
    // epilogue: chunks 30 (in A) and 31 (in B)
    asm volatile("cp.async.wait_group 1;\n" ::: "memory");
    __syncthreads();
    consume(cvA, amA, xstg[30 % 3]);
    asm volatile("cp.async.wait_group 0;\n" ::: "memory");
    __syncthreads();
    consume(cvB, amB, xstg[31 % 3]);

    // warp-reduce packed (even,odd) batch sums, store
    #pragma unroll
    for (int r = 0; r < RPW; ++r) {
        #pragma unroll
        for (int p = 0; p < NP; ++p) {
            float se, so;
            upk2(acc[r][p], se, so);
            #pragma unroll
            for (int off = 16; off > 0; off >>= 1) {
                se += __shfl_xor_sync(0xffffffffu, se, off);
                so += __shfl_xor_sync(0xffffffffu, so, off);
            }
            if (lane == 0) {
                out[(size_t)(2 * p)     * OUT_F + row0 + r] = se;
                out[(size_t)(2 * p + 1) * OUT_F + row0 + r] = so;
            }
        }
    }
}

extern "C" void kernel_launch(void* const* d_in, const int* in_sizes, int n_in,
                              void* d_out, int out_size) {
    const float* x      = (const float*)d_in[0];   // [8,1,4096] f32
    const int*   codes  = (const int*)d_in[1];     // [16384,4096] i32 (0..15)
    const float* absmax = (const float*)d_in[2];   // [16384,64] f32
    float*       out    = (float*)d_out;           // [8,1,16384] f32

    (void)in_sizes; (void)n_in; (void)out_size;
    xt_kernel<<<(NP * IN_F) / 256, 256>>>(x);
    nf4_qlinear_kernel<<<OUT_F / ROWS_PER_CTA, THREADS>>>(codes, absmax, out);
}

// round 16
// speedup vs baseline: 1.1799x; 1.1799x over previous
#include <cuda_runtime.h>
#include <cstdint>

#define IN_F  4096
#define OUT_F 16384
#define NB    8      // batch vectors
#define NP    (NB/2) // batch pairs
#define RPW   8      // rows per warp
#define WARPS 4
#define THREADS (WARPS * 32)          // 128
#define ROWS_PER_CTA (RPW * WARPS)    // 32
#define NCHUNK (IN_F / 128)           // 32 chunks (4 cols/lane each)
#define AROW   (IN_F / 64)            // absmax row stride (64)

__constant__ float NF4_CODE[16] = {
    -1.0f, -0.6961928009986877f, -0.5250730514526367f, -0.39491748809814453f,
    -0.28444138169288635f, -0.18477343022823334f, -0.09105003625154495f, 0.0f,
    0.07958029955625534f, 0.16093020141124725f, 0.24611230194568634f,
    0.33791524171829224f, 0.44070982933044434f, 0.5626170039176941f,
    0.7229568362236023f, 1.0f};

typedef unsigned long long ull;

// cross-batch packed x: g_xT[p*IN_F + col] = (x[2p][col], x[2p+1][col])
__device__ ull g_xT[NP * IN_F];

__device__ __forceinline__ ull pk2(float lo, float hi) {
    ull r;
    asm("mov.b64 %0, {%1, %2};" : "=l"(r)
        : "r"(__float_as_uint(lo)), "r"(__float_as_uint(hi)));
    return r;
}
__device__ __forceinline__ void upk2(ull v, float& lo, float& hi) {
    unsigned int a, b;
    asm("mov.b64 {%0, %1}, %2;" : "=r"(a), "=r"(b) : "l"(v));
    lo = __uint_as_float(a); hi = __uint_as_float(b);
}
__device__ __forceinline__ void fma2(ull& acc, ull a, ull b) {
    asm("fma.rn.f32x2 %0, %1, %2, %0;" : "+l"(acc) : "l"(a), "l"(b));
}
__device__ __forceinline__ ull mul2(ull a, ull b) {
    ull r;
    asm("mul.rn.f32x2 %0, %1, %2;" : "=l"(r) : "l"(a), "l"(b));
    return r;
}
__device__ __forceinline__ void pf_l1(const void* p) {
    asm volatile("prefetch.global.L1 [%0];" :: "l"(p));
}

// ---- prepass: build cross-batch packed x (once per launch, ~1.5us) ----
__global__ void xt_kernel(const float* __restrict__ x) {
    const int idx = blockIdx.x * 256 + threadIdx.x;   // 0 .. NP*IN_F-1
    const int p   = idx >> 12;
    const int col = idx & (IN_F - 1);
    g_xT[idx] = pk2(x[(2 * p) * IN_F + col], x[(2 * p + 1) * IN_F + col]);
}

__global__ __launch_bounds__(THREADS, 2)
void nf4_qlinear_kernel(const int*   __restrict__ codes,
                        const float* __restrict__ absmax,
                        float*       __restrict__ out) {
    // splat NF4 table: tabS[c] = (nf4[c], nf4[c]); disjoint bank pairs +
    // broadcast -> LDS.64 conflict-free for any code pattern
    __shared__ ull tabS[16];
    const int tid  = threadIdx.x;
    const int lane = tid & 31;
    const int warp = tid >> 5;
    if (tid < 16) tabS[tid] = pk2(NF4_CODE[tid], NF4_CODE[tid]);
    __syncthreads();

    const int row0   = blockIdx.x * ROWS_PER_CTA + warp * RPW;
    const int sel_hi = (lane >= 16);

    // pointer-bump bases (all loads reg + const-immediate offsets)
    const int4*  cp = reinterpret_cast<const int4*>(
                          codes + (size_t)row0 * IN_F) + lane;
    const float* ap = absmax + (size_t)row0 * AROW + sel_hi;
    const ull*   xp = g_xT + lane * 4;

    ull acc[RPW][NP];    // acc[r][p] packs (batch 2p, batch 2p+1)
    #pragma unroll
    for (int r = 0; r < RPW; ++r)
        #pragma unroll
        for (int p = 0; p < NP; ++p) acc[r][p] = 0ULL;

    // warm L1 with the xT slice of chunk (xp-relative offset xo)
    auto xprefetch = [&](int xo) {
        #pragma unroll
        for (int p = 0; p < NP; ++p)
            pf_l1(xp + xo + (size_t)p * IN_F);
    };

    // ---- consume one chunk from prefetched codes + absmax ----
    auto consume = [&](const int4* cv, const float* am, int xo) {
        ull xq0[NP], xq1[NP], xq2[NP], xq3[NP];
        #pragma unroll
        for (int p = 0; p < NP; ++p) {
            const ulonglong2 xv0 = *reinterpret_cast<const ulonglong2*>(
                xp + xo + (size_t)p * IN_F);
            const ulonglong2 xv1 = *reinterpret_cast<const ulonglong2*>(
                xp + xo + (size_t)p * IN_F + 2);
            xq0[p] = xv0.x; xq1[p] = xv0.y;
            xq2[p] = xv1.x; xq3[p] = xv1.y;
        }
        #pragma unroll
        for (int r = 0; r < RPW; ++r) {
            const ull a2 = pk2(am[r], am[r]);
            const ull s0 = mul2(tabS[cv[r].x], a2);
            const ull s1 = mul2(tabS[cv[r].y], a2);
            const ull s2 = mul2(tabS[cv[r].z], a2);
            const ull s3 = mul2(tabS[cv[r].w], a2);
            #pragma unroll
            for (int p = 0; p < NP; ++p) {
                fma2(acc[r][p], s0, xq0[p]);
                fma2(acc[r][p], s1, xq1[p]);
                fma2(acc[r][p], s2, xq2[p]);
                fma2(acc[r][p], s3, xq3[p]);
            }
        }
    };

    // ---- distance-2 triple-buffered prefetch, unrolled x3 ----
    int4  cvA[RPW], cvB[RPW], cvC[RPW];
    float amA[RPW], amB[RPW], amC[RPW];
    #pragma unroll
    for (int r = 0; r < RPW; ++r) {          // chunks 0 and 1
        cvA[r] = __ldcs(cp + r * (IN_F / 4));
        amA[r] = __ldg(ap + r * AROW);
        cvB[r] = __ldcs(cp + 32 + r * (IN_F / 4));
        amB[r] = __ldg(ap + 2 + r * AROW);
    }
    xprefetch(0);
    xprefetch(128);

    #pragma unroll 1
    for (int it = 0; it < 10; ++it) {        // chunks 3*it .. 3*it+2
        #pragma unroll
        for (int r = 0; r < RPW; ++r) {      // prefetch codes j+2
            cvC[r] = __ldcs(cp + 64 + r * (IN_F / 4));
            amC[r] = __ldg(ap + 4 + r * AROW);
        }
        xprefetch(256);                       // x for chunk j+2
        consume(cvA, amA, 0);
        #pragma unroll
        for (int r = 0; r < RPW; ++r) {      // prefetch codes j+3
            cvA[r] = __ldcs(cp + 96 + r * (IN_F / 4));
            amA[r] = __ldg(ap + 6 + r * AROW);
        }
        xprefetch(384);                       // x for chunk j+3
        consume(cvB, amB, 128);
        #pragma unroll
        for (int r = 0; r < RPW; ++r) {      // prefetch codes j+4
            cvB[r] = __ldcs(cp + 128 + r * (IN_F / 4));
            amB[r] = __ldg(ap + 8 + r * AROW);
        }
        xprefetch(512);                       // x for chunk j+4
        consume(cvC, amC, 256);
        cp += 96;     // 3 chunks
        ap += 6;
        xp += 384;
    }
    // epilogue: chunks 30 (in A) and 31 (in B)
    consume(cvA, amA, 0);
    consume(cvB, amB, 128);

    // warp-reduce packed (even,odd) batch sums, store
    #pragma unroll
    for (int r = 0; r < RPW; ++r) {
        #pragma unroll
        for (int p = 0; p < NP; ++p) {
            float se, so;
            upk2(acc[r][p], se, so);
            #pragma unroll
            for (int off = 16; off > 0; off >>= 1) {
                se += __shfl_xor_sync(0xffffffffu, se, off);
                so += __shfl_xor_sync(0xffffffffu, so, off);
            }
            if (lane == 0) {
                out[(size_t)(2 * p)     * OUT_F + row0 + r] = se;
                out[(size_t)(2 * p + 1) * OUT_F + row0 + r] = so;
            }
        }
    }
}

extern "C" void kernel_launch(void* const* d_in, const int* in_sizes, int n_in,
                              void* d_out, int out_size) {
    const float* x      = (const float*)d_in[0];   // [8,1,4096] f32
    const int*   codes  = (const int*)d_in[1];     // [16384,4096] i32 (0..15)
    const float* absmax = (const float*)d_in[2];   // [16384,64] f32
    float*       out    = (float*)d_out;           // [8,1,16384] f32

    (void)in_sizes; (void)n_in; (void)out_size;
    xt_kernel<<<(NP * IN_F) / 256, 256>>>(x);
    nf4_qlinear_kernel<<<OUT_F / ROWS_PER_CTA, THREADS>>>(codes, absmax, out);
}

// round 17
// speedup vs baseline: 1.8072x; 1.5317x over previous
#include <cuda_runtime.h>
#include <cstdint>

#define IN_F  4096
#define OUT_F 16384
#define NB    8      // batch vectors
#define NP    (NB/2) // batch pairs
#define RPW   8      // rows per warp
#define WARPS 4
#define THREADS (WARPS * 32)          // 128
#define ROWS_PER_CTA (RPW * WARPS)    // 32
#define NCHUNK (IN_F / 128)           // 32 chunks (4 cols/lane each)
#define AROW   (IN_F / 64)            // absmax row stride (64)
#define PROW   (IN_F / 2)             // ull per pair per plane (2048)

__constant__ float NF4_CODE[16] = {
    -1.0f, -0.6961928009986877f, -0.5250730514526367f, -0.39491748809814453f,
    -0.28444138169288635f, -0.18477343022823334f, -0.09105003625154495f, 0.0f,
    0.07958029955625534f, 0.16093020141124725f, 0.24611230194568634f,
    0.33791524171829224f, 0.44070982933044434f, 0.5626170039176941f,
    0.7229568362236023f, 1.0f};

typedef unsigned long long ull;

// dual-plane cross-batch packed x (perfectly coalesced 16B/lane loads):
// for chunk j, lane l, pair p:
//   g_xA[p*PROW + j*64 + l*2 + {0,1}] = packed cols (c, c+1),   c = j*128+l*4
//   g_xB[p*PROW + j*64 + l*2 + {0,1}] = packed cols (c+2, c+3)
__device__ ull g_xA[NP * PROW];
__device__ ull g_xB[NP * PROW];

__device__ __forceinline__ ull pk2(float lo, float hi) {
    ull r;
    asm("mov.b64 %0, {%1, %2};" : "=l"(r)
        : "r"(__float_as_uint(lo)), "r"(__float_as_uint(hi)));
    return r;
}
__device__ __forceinline__ void upk2(ull v, float& lo, float& hi) {
    unsigned int a, b;
    asm("mov.b64 {%0, %1}, %2;" : "=r"(a), "=r"(b) : "l"(v));
    lo = __uint_as_float(a); hi = __uint_as_float(b);
}
__device__ __forceinline__ void fma2(ull& acc, ull a, ull b) {
    asm("fma.rn.f32x2 %0, %1, %2, %0;" : "+l"(acc) : "l"(a), "l"(b));
}
__device__ __forceinline__ ull mul2(ull a, ull b) {
    ull r;
    asm("mul.rn.f32x2 %0, %1, %2;" : "=l"(r) : "l"(a), "l"(b));
    return r;
}

// ---- prepass: build dual-plane packed x (once per launch, ~1.5us) ----
__global__ void xt_kernel(const float* __restrict__ x) {
    const int idx = blockIdx.x * 256 + threadIdx.x;   // 0 .. NP*IN_F-1
    const int p   = idx >> 12;
    const int col = idx & (IN_F - 1);
    const ull v   = pk2(x[(2 * p) * IN_F + col], x[(2 * p + 1) * IN_F + col]);
    const int j     = col >> 7;          // chunk
    const int l     = (col & 127) >> 2;  // lane
    const int rem   = col & 3;
    const int dst   = p * PROW + j * 64 + l * 2 + (rem & 1);
    if (rem < 2) g_xA[dst] = v;
    else         g_xB[dst] = v;
}

__global__ __launch_bounds__(THREADS, 2)
void nf4_qlinear_kernel(const int*   __restrict__ codes,
                        const float* __restrict__ absmax,
                        float*       __restrict__ out) {
    // splat NF4 table: tabS[c] = (nf4[c], nf4[c]); disjoint bank pairs +
    // broadcast -> LDS.64 conflict-free for any code pattern
    __shared__ ull tabS[16];
    const int tid  = threadIdx.x;
    const int lane = tid & 31;
    const int warp = tid >> 5;
    if (tid < 16) tabS[tid] = pk2(NF4_CODE[tid], NF4_CODE[tid]);
    __syncthreads();

    const int row0   = blockIdx.x * ROWS_PER_CTA + warp * RPW;
    const int sel_hi = (lane >= 16);

    // pointer-bump bases (all loads reg + const-immediate offsets)
    const int4*  cp = reinterpret_cast<const int4*>(
                          codes + (size_t)row0 * IN_F) + lane;
    const float* ap = absmax + (size_t)row0 * AROW + sel_hi;
    const ull*   xa = g_xA + lane * 2;
    const ull*   xb = g_xB + lane * 2;

    ull acc[RPW][NP];    // acc[r][p] packs (batch 2p, batch 2p+1)
    #pragma unroll
    for (int r = 0; r < RPW; ++r)
        #pragma unroll
        for (int p = 0; p < NP; ++p) acc[r][p] = 0ULL;

    // ---- consume one chunk from prefetched codes + absmax ----
    auto consume = [&](const int4* cv, const float* am, int xo) {
        ull xq0[NP], xq1[NP], xq2[NP], xq3[NP];
        #pragma unroll
        for (int p = 0; p < NP; ++p) {
            const ulonglong2 va = *reinterpret_cast<const ulonglong2*>(
                xa + xo + (size_t)p * PROW);
            const ulonglong2 vb = *reinterpret_cast<const ulonglong2*>(
                xb + xo + (size_t)p * PROW);
            xq0[p] = va.x; xq1[p] = va.y;
            xq2[p] = vb.x; xq3[p] = vb.y;
        }
        #pragma unroll
        for (int r = 0; r < RPW; ++r) {
            const ull a2 = pk2(am[r], am[r]);
            const ull s0 = mul2(tabS[cv[r].x], a2);
            const ull s1 = mul2(tabS[cv[r].y], a2);
            const ull s2 = mul2(tabS[cv[r].z], a2);
            const ull s3 = mul2(tabS[cv[r].w], a2);
            #pragma unroll
            for (int p = 0; p < NP; ++p) {
                fma2(acc[r][p], s0, xq0[p]);
                fma2(acc[r][p], s1, xq1[p]);
                fma2(acc[r][p], s2, xq2[p]);
                fma2(acc[r][p], s3, xq3[p]);
            }
        }
    };

    // ---- distance-2 triple-buffered prefetch, unrolled x3 ----
    int4  cvA[RPW], cvB[RPW], cvC[RPW];
    float amA[RPW], amB[RPW], amC[RPW];
    #pragma unroll
    for (int r = 0; r < RPW; ++r) {          // chunks 0 and 1
        cvA[r] = __ldcs(cp + r * (IN_F / 4));
        amA[r] = __ldg(ap + r * AROW);
        cvB[r] = __ldcs(cp + 32 + r * (IN_F / 4));
        amB[r] = __ldg(ap + 2 + r * AROW);
    }

    #pragma unroll 1
    for (int it = 0; it < 10; ++it) {        // chunks 3*it .. 3*it+2
        #pragma unroll
        for (int r = 0; r < RPW; ++r) {      // prefetch codes j+2
            cvC[r] = __ldcs(cp + 64 + r * (IN_F / 4));
            amC[r] = __ldg(ap + 4 + r * AROW);
        }
        consume(cvA, amA, 0);
        #pragma unroll
        for (int r = 0; r < RPW; ++r) {      // prefetch codes j+3
            cvA[r] = __ldcs(cp + 96 + r * (IN_F / 4));
            amA[r] = __ldg(ap + 6 + r * AROW);
        }
        consume(cvB, amB, 64);
        #pragma unroll
        for (int r = 0; r < RPW; ++r) {      // prefetch codes j+4
            cvB[r] = __ldcs(cp + 128 + r * (IN_F / 4));
            amB[r] = __ldg(ap + 8 + r * AROW);
        }
        consume(cvC, amC, 128);
        cp += 96;     // 3 chunks
        ap += 6;
        xa += 192;
        xb += 192;
    }
    // epilogue: chunks 30 (in A) and 31 (in B)
    consume(cvA, amA, 0);
    consume(cvB, amB, 64);

    // warp-reduce packed (even,odd) batch sums, store
    #pragma unroll
    for (int r = 0; r < RPW; ++r) {
        #pragma unroll
        for (int p = 0; p < NP; ++p) {
            float se, so;
            upk2(acc[r][p], se, so);
            #pragma unroll
            for (int off = 16; off > 0; off >>= 1) {
                se += __shfl_xor_sync(0xffffffffu, se, off);
                so += __shfl_xor_sync(0xffffffffu, so, off);
            }
            if (lane == 0) {
                out[(size_t)(2 * p)     * OUT_F + row0 + r] = se;
                out[(size_t)(2 * p + 1) * OUT_F + row0 + r] = so;
            }
        }
    }
}

extern "C" void kernel_launch(void* const* d_in, const int* in_sizes, int n_in,
                              void* d_out, int out_size) {
    const float* x      = (const float*)d_in[0];   // [8,1,4096] f32
    const int*   codes  = (const int*)d_in[1];     // [16384,4096] i32 (0..15)
    const float* absmax = (const float*)d_in[2];   // [16384,64] f32
    float*       out    = (float*)d_out;           // [8,1,16384] f32

    (void)in_sizes; (void)n_in; (void)out_size;
    xt_kernel<<<(NP * IN_F) / 256, 256>>>(x);
    nf4_qlinear_kernel<<<OUT_F / ROWS_PER_CTA, THREADS>>>(codes, absmax, out);
}